// round 6
// baseline (speedup 1.0000x reference)
#include <cuda_runtime.h>
#include <math.h>

// Problem constants
#define BB    64
#define FF    1024
#define HIDD  2048
#define NHH   4
#define HDD   512
#define KSS   4
#define EPSF  1e-6f
#define INV_SQRT_HD 0.04419417382415922f   // 1/sqrt(512)

#define UP_SPLITK   4
#define DOWN_SPLITK 8
#define UPSZ   (BB*2*HIDD)          // 64*4096 elements per up partial slice

// ---------------- scratch (__device__ globals: allocation-free) ----------------
__device__ float g_up[UP_SPLITK*UPSZ];     // up-proj split-K partials (x|z)
__device__ float g_convact[BB*HIDD];
__device__ float g_q[BB*HIDD];
__device__ float g_k[BB*HIDD];
__device__ float g_v[BB*HIDD];
__device__ float g_fp[BB*NHH];
__device__ float g_ip[BB*NHH];
__device__ float g_emn[BB*NHH];  // exp(-m_new)
__device__ float g_nom[BB*HIDD]; // q^T @ C_new
__device__ float g_den[BB*NHH];  // q^T @ n_new
__device__ float g_h[BB*HIDD];

// =====================================================================
// Skinny SGEMM, split-K partials (no atomics): part[slice][64 x N]
// Tile 64 x 64 x 16, 256 threads, 4x4 microtile, float4 smem loads.
// =====================================================================
__global__ void sgemm_m64_part(const float* __restrict__ A, const float* __restrict__ Bm,
                               int K, int N, int Kslice, float* __restrict__ part)
{
    __shared__ float As[16][64];
    __shared__ float Bs[16][64];
    int tid = threadIdx.x;              // 256
    int tm = tid >> 4, tn = tid & 15;   // 16x16 threads -> 4 rows x 4 cols each
    float acc[4][4] = {};
    int nb = blockIdx.x * 64;
    int kbeg = blockIdx.y * Kslice;
    int kend = kbeg + Kslice;

    int arow = tid & 63, ak4 = (tid >> 6) * 4;   // A: 64x16 transpose store
    int brow = tid >> 4, bcol = (tid & 15) * 4;  // B: 16x64 float4

    for (int k0 = kbeg; k0 < kend; k0 += 16) {
        float4 a4 = *(const float4*)(A + (size_t)arow * K + k0 + ak4);
        As[ak4+0][arow] = a4.x; As[ak4+1][arow] = a4.y;
        As[ak4+2][arow] = a4.z; As[ak4+3][arow] = a4.w;
        *(float4*)&Bs[brow][bcol] = *(const float4*)(Bm + (size_t)(k0 + brow) * N + nb + bcol);
        __syncthreads();
#pragma unroll
        for (int kk = 0; kk < 16; kk++) {
            float4 a = *(const float4*)&As[kk][tm*4];
            float4 b = *(const float4*)&Bs[kk][tn*4];
            acc[0][0] += a.x*b.x; acc[0][1] += a.x*b.y; acc[0][2] += a.x*b.z; acc[0][3] += a.x*b.w;
            acc[1][0] += a.y*b.x; acc[1][1] += a.y*b.y; acc[1][2] += a.y*b.z; acc[1][3] += a.y*b.w;
            acc[2][0] += a.z*b.x; acc[2][1] += a.z*b.y; acc[2][2] += a.z*b.z; acc[2][3] += a.z*b.w;
            acc[3][0] += a.w*b.x; acc[3][1] += a.w*b.y; acc[3][2] += a.w*b.z; acc[3][3] += a.w*b.w;
        }
        __syncthreads();
    }
    float* dst = part + (size_t)blockIdx.y * 64 * N;
#pragma unroll
    for (int i = 0; i < 4; i++) {
        float4 v = make_float4(acc[i][0], acc[i][1], acc[i][2], acc[i][3]);
        *(float4*)(dst + (size_t)(tm*4 + i) * N + nb + tn*4) = v;
    }
}

// =====================================================================
// Same GEMM, but epilogue reduces into a single output with atomicAdd
// (RED.GLOBAL, no return). out must be pre-zeroed (finalize does it).
// =====================================================================
__global__ void sgemm_m64_red(const float* __restrict__ A, const float* __restrict__ Bm,
                              int K, int N, int Kslice, float* __restrict__ out)
{
    __shared__ float As[16][64];
    __shared__ float Bs[16][64];
    int tid = threadIdx.x;
    int tm = tid >> 4, tn = tid & 15;
    float acc[4][4] = {};
    int nb = blockIdx.x * 64;
    int kbeg = blockIdx.y * Kslice;
    int kend = kbeg + Kslice;

    int arow = tid & 63, ak4 = (tid >> 6) * 4;
    int brow = tid >> 4, bcol = (tid & 15) * 4;

    for (int k0 = kbeg; k0 < kend; k0 += 16) {
        float4 a4 = *(const float4*)(A + (size_t)arow * K + k0 + ak4);
        As[ak4+0][arow] = a4.x; As[ak4+1][arow] = a4.y;
        As[ak4+2][arow] = a4.z; As[ak4+3][arow] = a4.w;
        *(float4*)&Bs[brow][bcol] = *(const float4*)(Bm + (size_t)(k0 + brow) * N + nb + bcol);
        __syncthreads();
#pragma unroll
        for (int kk = 0; kk < 16; kk++) {
            float4 a = *(const float4*)&As[kk][tm*4];
            float4 b = *(const float4*)&Bs[kk][tn*4];
            acc[0][0] += a.x*b.x; acc[0][1] += a.x*b.y; acc[0][2] += a.x*b.z; acc[0][3] += a.x*b.w;
            acc[1][0] += a.y*b.x; acc[1][1] += a.y*b.y; acc[1][2] += a.y*b.z; acc[1][3] += a.y*b.w;
            acc[2][0] += a.z*b.x; acc[2][1] += a.z*b.y; acc[2][2] += a.z*b.z; acc[2][3] += a.z*b.w;
            acc[3][0] += a.w*b.x; acc[3][1] += a.w*b.y; acc[3][2] += a.w*b.z; acc[3][3] += a.w*b.w;
        }
        __syncthreads();
    }
#pragma unroll
    for (int i = 0; i < 4; i++) {
        float* row = out + (size_t)(tm*4 + i) * N + nb + tn*4;
        atomicAdd(row+0, acc[i][0]);
        atomicAdd(row+1, acc[i][1]);
        atomicAdd(row+2, acc[i][2]);
        atomicAdd(row+3, acc[i][3]);
    }
}

// =====================================================================
// Per-batch prep: combine up-proj x-partials, conv-state shift,
// causal conv + silu, block-diag q/k/v, gate dots, m_new/f_p/i_p.
// Zeroes g_nom / g_den. One block per batch, 256 threads.
// =====================================================================
__global__ void prep_kernel(const float* __restrict__ conv_state,
                            const float* __restrict__ conv_w,
                            const float* __restrict__ conv_b,
                            const float* __restrict__ Wq,
                            const float* __restrict__ Wk,
                            const float* __restrict__ Wv,
                            const float* __restrict__ Wi,
                            const float* __restrict__ bi,
                            const float* __restrict__ Wf,
                            const float* __restrict__ bf,
                            const float* __restrict__ m_in,
                            float* __restrict__ out_cs,
                            float* __restrict__ out_m)
{
    __shared__ float s_x[HIDD];
    __shared__ float s_conv[HIDD];
    __shared__ float s_qkv[3*HIDD];
    __shared__ float s_red[64];
    __shared__ float s_fin[8];

    int b = blockIdx.x;
    int tid = threadIdx.x;
    const float* cs  = conv_state + (size_t)b*KSS*HIDD;
    float*       ocs = out_cs     + (size_t)b*KSS*HIDD;
    const float* up  = g_up + (size_t)b*(2*HIDD);

    for (int j = tid; j < HIDD; j += 256) {
        float u0 = up[j], u1 = up[UPSZ + j], u2 = up[2*UPSZ + j], u3 = up[3*UPSZ + j];
        float c1 = cs[1*HIDD + j], c2 = cs[2*HIDD + j], c3 = cs[3*HIDD + j];
        float xj = u0 + u1 + u2 + u3;
        s_x[j] = xj;
        ocs[0*HIDD + j] = c1;
        ocs[1*HIDD + j] = c2;
        ocs[2*HIDD + j] = c3;
        ocs[3*HIDD + j] = xj;
        float conv = c1*conv_w[0*HIDD+j] + c2*conv_w[1*HIDD+j]
                   + c3*conv_w[2*HIDD+j] + xj*conv_w[3*HIDD+j] + conv_b[j];
        float act = conv / (1.f + expf(-conv));   // silu
        s_conv[j] = act;
        g_convact[b*HIDD + j] = act;
        g_nom[b*HIDD + j] = 0.f;
    }
    if (tid < NHH) g_den[b*NHH + tid] = 0.f;
    __syncthreads();

    // block-diagonal q/k/v (4x4 blocks)
    for (int j = tid; j < HIDD; j += 256) {
        int nb4 = j >> 2, e = j & 3;
        const float* wq = Wq + nb4*16 + e;
        const float* wk = Wk + nb4*16 + e;
        const float* wv = Wv + nb4*16 + e;
        float a0 = s_conv[nb4*4+0], a1 = s_conv[nb4*4+1], a2 = s_conv[nb4*4+2], a3 = s_conv[nb4*4+3];
        float x0 = s_x[nb4*4+0],    x1 = s_x[nb4*4+1],    x2 = s_x[nb4*4+2],    x3 = s_x[nb4*4+3];
        float q = a0*wq[0] + a1*wq[4] + a2*wq[8] + a3*wq[12];
        float k = a0*wk[0] + a1*wk[4] + a2*wk[8] + a3*wk[12];
        float v = x0*wv[0] + x1*wv[4] + x2*wv[8] + x3*wv[12];
        s_qkv[j]          = q;
        s_qkv[HIDD + j]   = k;
        s_qkv[2*HIDD + j] = v;
        g_q[b*HIDD + j] = q;
        g_k[b*HIDD + j] = k;
        g_v[b*HIDD + j] = v;
    }
    __syncthreads();

    // gates
    float pi[NHH] = {0,0,0,0};
    float pf[NHH] = {0,0,0,0};
    const float4* Wi4 = (const float4*)Wi;
    const float4* Wf4 = (const float4*)Wf;
    for (int j = tid; j < 3*HIDD; j += 256) {
        float val = s_qkv[j];
        float4 wi = Wi4[j];
        float4 wf = Wf4[j];
        pi[0] += val*wi.x; pi[1] += val*wi.y; pi[2] += val*wi.z; pi[3] += val*wi.w;
        pf[0] += val*wf.x; pf[1] += val*wf.y; pf[2] += val*wf.z; pf[3] += val*wf.w;
    }
#pragma unroll
    for (int off = 16; off; off >>= 1) {
#pragma unroll
        for (int h = 0; h < NHH; h++) {
            pi[h] += __shfl_down_sync(0xffffffffu, pi[h], off);
            pf[h] += __shfl_down_sync(0xffffffffu, pf[h], off);
        }
    }
    int lane = tid & 31, warp = tid >> 5;
    if (lane == 0) {
#pragma unroll
        for (int h = 0; h < NHH; h++) {
            s_red[warp*8 + h]     = pi[h];
            s_red[warp*8 + 4 + h] = pf[h];
        }
    }
    __syncthreads();
    if (tid < 8) {
        float s = 0.f;
#pragma unroll
        for (int w = 0; w < 8; w++) s += s_red[w*8 + tid];
        s_fin[tid] = s;
    }
    __syncthreads();
    if (tid < NHH) {
        int h = tid;
        float it = s_fin[h]     + bi[h];
        float ft = s_fin[4 + h] + bf[h];
        float logf = (ft > 0.f) ? -log1pf(expf(-ft)) : (ft - log1pf(expf(ft)));
        float mo = m_in[b*NHH + h];
        float mn = fmaxf(logf + mo, it);
        out_m[b*NHH + h] = mn;
        g_ip[b*NHH + h]  = expf(it - mn);
        g_fp[b*NHH + h]  = expf(logf + mo - mn);
        g_emn[b*NHH + h] = expf(-mn);
    }
}

// =====================================================================
// Fused C-state stream (the 537 MB). 32-row chunks: grid (16, B*NH)
// = 4096 blocks x 256 threads for tighter waves / smaller tail.
// n_new/den tail hoisted BEFORE the stream loop so it hides under it.
// =====================================================================
__global__ void c_update_kernel(const float* __restrict__ C,
                                const float* __restrict__ n_in,
                                float* __restrict__ outC,
                                float* __restrict__ outN)
{
    int bh = blockIdx.y;
    int d0 = blockIdx.x * 32;
    int tid = threadIdx.x;  // 256

    __shared__ float s_kh[32];
    __shared__ float s_q[32];

    float fp = g_fp[bh];
    float ip = g_ip[bh];

    if (tid < 32) {
        int d = d0 + tid;
        float kh = g_k[bh*HDD + d] * INV_SQRT_HD;
        s_kh[tid] = kh;
        s_q[tid]  = g_q[bh*HDD + d];
    }
    __syncthreads();

    // n_new + den partial for this chunk's 32 rows (hidden under the stream)
    if (tid < 32) {
        int d = d0 + tid;
        float nn = fp * n_in[bh*HDD + d] + ip * s_kh[tid];
        outN[bh*HDD + d] = nn;
        float p = s_q[tid] * nn;
#pragma unroll
        for (int off = 16; off; off >>= 1) p += __shfl_down_sync(0xffffffffu, p, off);
        if (tid == 0) atomicAdd(&g_den[bh], p);
    }

    int tx = tid & 127;   // column group (x4 -> 512 cols)
    int ty = tid >> 7;    // row interleave
    float4 v4 = *(const float4*)(g_v + bh*HDD + tx*4);

    const float4* Cb = (const float4*)(C    + (size_t)bh*HDD*HDD);
    float4*       Ob = (float4*)      (outC + (size_t)bh*HDD*HDD);

    float4 acc = make_float4(0.f, 0.f, 0.f, 0.f);
#pragma unroll 8
    for (int dd = ty; dd < 32; dd += 2) {
        int d = d0 + dd;
        size_t idx = (size_t)d * (HDD/4) + tx;
        float4 c = __ldcs(Cb + idx);
        float ipk = ip * s_kh[dd];
        float4 cn;
        cn.x = fp*c.x + ipk*v4.x;
        cn.y = fp*c.y + ipk*v4.y;
        cn.z = fp*c.z + ipk*v4.z;
        cn.w = fp*c.w + ipk*v4.w;
        __stcs(Ob + idx, cn);
        float qd = s_q[dd];
        acc.x += qd*cn.x;
        acc.y += qd*cn.y;
        acc.z += qd*cn.z;
        acc.w += qd*cn.w;
    }
    float* nomp = g_nom + bh*HDD + tx*4;
    atomicAdd(nomp+0, acc.x);
    atomicAdd(nomp+1, acc.y);
    atomicAdd(nomp+2, acc.z);
    atomicAdd(nomp+3, acc.w);
}

// =====================================================================
// Finalize per (b,h): h_tilde = nom/(den+eps), layernorm over HD,
// + skip*conv_act, * silu(z) -> g_h.  All independent LDGs issued up
// front (MLP~12) to cut dependent-latency serialization.
// Also zeroes out_y so the down-GEMM can use a RED epilogue.
// grid = B*NH, 128 threads.
// =====================================================================
__global__ void finalize_kernel(const float* __restrict__ norm_scale,
                                const float* __restrict__ skip,
                                float* __restrict__ out_y)
{
    int bh = blockIdx.x;
    int b = bh >> 2, h = bh & 3;
    int tid = threadIdx.x;  // 128

    __shared__ float ss[4], ss2[4];
    __shared__ float s_mean, s_rstd;

    // ---- issue ALL independent loads first ----
    float  denp = g_den[bh];
    float  emn  = g_emn[bh];
    float4 nom4 = *(const float4*)(g_nom + bh*HDD + tid*4);
    const float* zb = g_up + (size_t)b*(2*HIDD) + HIDD + h*HDD + tid*4;
    float4 za = *(const float4*)(zb + 0*UPSZ);
    float4 zc = *(const float4*)(zb + 1*UPSZ);
    float4 zd = *(const float4*)(zb + 2*UPSZ);
    float4 ze = *(const float4*)(zb + 3*UPSZ);
    float4 ca  = *(const float4*)(g_convact + b*HIDD + h*HDD + tid*4);
    float4 sk4 = *(const float4*)(skip + h*HDD + tid*4);
    float4 ns4 = *(const float4*)(norm_scale + h*HDD + tid*4);

    // zero out_y (64K floats over 256 blocks x 128 threads x float2)
    ((float2*)out_y)[bh*128 + tid] = make_float2(0.f, 0.f);

    float den = fmaxf(fabsf(denp), emn) + EPSF;
    float inv = 1.f / den;

    float4 ht;
    ht.x = nom4.x * inv; ht.y = nom4.y * inv; ht.z = nom4.z * inv; ht.w = nom4.w * inv;

    float s  = ht.x + ht.y + ht.z + ht.w;
    float s2 = ht.x*ht.x + ht.y*ht.y + ht.z*ht.z + ht.w*ht.w;
#pragma unroll
    for (int off = 16; off; off >>= 1) {
        s  += __shfl_down_sync(0xffffffffu, s,  off);
        s2 += __shfl_down_sync(0xffffffffu, s2, off);
    }
    int lane = tid & 31, warp = tid >> 5;
    if (lane == 0) { ss[warp] = s; ss2[warp] = s2; }
    __syncthreads();
    if (tid == 0) {
        float S  = ss[0] + ss[1] + ss[2] + ss[3];
        float S2 = ss2[0] + ss2[1] + ss2[2] + ss2[3];
        float mean = S / (float)HDD;
        float var  = S2 / (float)HDD - mean*mean;
        s_mean = mean;
        s_rstd = rsqrtf(var + EPSF);
    }
    __syncthreads();
    float mean = s_mean, rstd = s_rstd;

    float zv[4];
    zv[0] = za.x + zc.x + zd.x + ze.x;
    zv[1] = za.y + zc.y + zd.y + ze.y;
    zv[2] = za.z + zc.z + zd.z + ze.z;
    zv[3] = za.w + zc.w + zd.w + ze.w;
    float cv[4] = {ca.x, ca.y, ca.z, ca.w};
    float sv[4] = {sk4.x, sk4.y, sk4.z, sk4.w};
    float nv[4] = {ns4.x, ns4.y, ns4.z, ns4.w};
    float hv[4] = {ht.x, ht.y, ht.z, ht.w};

    float4 outv;
    float* po = (float*)&outv;
#pragma unroll
    for (int i = 0; i < 4; i++) {
        float hn = (hv[i] - mean) * rstd * nv[i];
        float hh = hn + sv[i] * cv[i];
        float z = zv[i];
        hh *= z / (1.f + expf(-z));
        po[i] = hh;
    }
    *(float4*)(g_h + b*HIDD + h*HDD + tid*4) = outv;
}

// =====================================================================
extern "C" void kernel_launch(void* const* d_in, const int* in_sizes, int n_in,
                              void* d_out, int out_size)
{
    const float* inputs     = (const float*)d_in[0];
    const float* C          = (const float*)d_in[1];
    const float* n_state    = (const float*)d_in[2];
    const float* m_state    = (const float*)d_in[3];
    const float* conv_state = (const float*)d_in[4];
    const float* W_up       = (const float*)d_in[5];
    const float* conv_w     = (const float*)d_in[6];
    const float* conv_b     = (const float*)d_in[7];
    const float* Wq         = (const float*)d_in[8];
    const float* Wk         = (const float*)d_in[9];
    const float* Wv         = (const float*)d_in[10];
    const float* Wi         = (const float*)d_in[11];
    const float* bi         = (const float*)d_in[12];
    const float* Wf         = (const float*)d_in[13];
    const float* bf         = (const float*)d_in[14];
    const float* norm_scale = (const float*)d_in[15];
    const float* skip       = (const float*)d_in[16];
    const float* W_down     = (const float*)d_in[17];

    float* out = (float*)d_out;
    // Output layout: y | C_new | n_new | m_new | conv_state_new
    float* out_y  = out;
    float* out_C  = out_y + (size_t)BB*FF;
    float* out_n  = out_C + (size_t)BB*NHH*HDD*HDD;
    float* out_m  = out_n + (size_t)BB*NHH*HDD;
    float* out_cs = out_m + (size_t)BB*NHH;

    float *pup, *ph;
    cudaGetSymbolAddress((void**)&pup, g_up);
    cudaGetSymbolAddress((void**)&ph, g_h);

    // 1) up-projection: [64,1024] @ [1024,4096] -> partials (split-K=4)
    sgemm_m64_part<<<dim3((2*HIDD)/64, UP_SPLITK), 256>>>(inputs, W_up, FF, 2*HIDD,
                                                          FF/UP_SPLITK, pup);

    // 2) conv / qkv / gates (combines x-partials)
    prep_kernel<<<BB, 256>>>(conv_state, conv_w, conv_b, Wq, Wk, Wv,
                             Wi, bi, Wf, bf, m_state, out_cs, out_m);

    // 3) fused C-state stream (the 537 MB)
    c_update_kernel<<<dim3(16, BB*NHH), 256>>>(C, n_state, out_C, out_n);

    // 4) h_tilde + layernorm + skip + z-gate; zeroes out_y for step 5
    finalize_kernel<<<BB*NHH, 128>>>(norm_scale, skip, out_y);

    // 5) down-projection: [64,2048] @ [2048,1024], RED epilogue into out_y
    sgemm_m64_red<<<dim3(FF/64, DOWN_SPLITK), 256>>>(ph, W_down, HIDD, FF,
                                                     HIDD/DOWN_SPLITK, out_y);
}

// round 8
// speedup vs baseline: 1.1134x; 1.1134x over previous
#include <cuda_runtime.h>
#include <math.h>

// Problem constants
#define BB    64
#define FF    1024
#define HIDD  2048
#define NHH   4
#define HDD   512
#define KSS   4
#define EPSF  1e-6f
#define INV_SQRT_HD 0.04419417382415922f   // 1/sqrt(512)

#define UP_SPLITK   4
#define DOWN_SPLITK 8
#define NCHUNK      8                        // c_update d-chunks (64 rows each)
#define UPSZ   (BB*2*HIDD)          // 64*4096 elements per up partial slice
#define DNSZ   (BB*FF)              // 64*1024 elements per down partial slice

// ---------------- scratch (__device__ globals: allocation-free) ----------------
__device__ float g_up[UP_SPLITK*UPSZ];     // up-proj split-K partials (x|z)
__device__ float g_down[DOWN_SPLITK*DNSZ]; // down-proj split-K partials
__device__ float g_convact[BB*HIDD];
__device__ float g_q[BB*HIDD];
__device__ float g_k[BB*HIDD];
__device__ float g_v[BB*HIDD];
__device__ float g_fp[BB*NHH];
__device__ float g_ip[BB*NHH];
__device__ float g_emn[BB*NHH];                  // exp(-m_new)
__device__ float g_nomp[NCHUNK*BB*NHH*HDD];      // q^T C_new partials, per chunk (no atomics)
__device__ float g_den[BB*NHH];                  // q^T @ n_new
__device__ float g_h[BB*HIDD];

// =====================================================================
// Skinny SGEMM, split-K partials (no atomics): part[slice][64 x N]
// Tile 64 x 64 x 16, 256 threads, 4x4 microtile, float4 smem loads.
// =====================================================================
__global__ void sgemm_m64_part(const float* __restrict__ A, const float* __restrict__ Bm,
                               int K, int N, int Kslice, float* __restrict__ part)
{
    __shared__ float As[16][64];
    __shared__ float Bs[16][64];
    int tid = threadIdx.x;              // 256
    int tm = tid >> 4, tn = tid & 15;   // 16x16 threads -> 4 rows x 4 cols each
    float acc[4][4] = {};
    int nb = blockIdx.x * 64;
    int kbeg = blockIdx.y * Kslice;
    int kend = kbeg + Kslice;

    int arow = tid & 63, ak4 = (tid >> 6) * 4;   // A: 64x16 transpose store
    int brow = tid >> 4, bcol = (tid & 15) * 4;  // B: 16x64 float4

    for (int k0 = kbeg; k0 < kend; k0 += 16) {
        float4 a4 = *(const float4*)(A + (size_t)arow * K + k0 + ak4);
        As[ak4+0][arow] = a4.x; As[ak4+1][arow] = a4.y;
        As[ak4+2][arow] = a4.z; As[ak4+3][arow] = a4.w;
        *(float4*)&Bs[brow][bcol] = *(const float4*)(Bm + (size_t)(k0 + brow) * N + nb + bcol);
        __syncthreads();
#pragma unroll
        for (int kk = 0; kk < 16; kk++) {
            float4 a = *(const float4*)&As[kk][tm*4];
            float4 b = *(const float4*)&Bs[kk][tn*4];
            acc[0][0] += a.x*b.x; acc[0][1] += a.x*b.y; acc[0][2] += a.x*b.z; acc[0][3] += a.x*b.w;
            acc[1][0] += a.y*b.x; acc[1][1] += a.y*b.y; acc[1][2] += a.y*b.z; acc[1][3] += a.y*b.w;
            acc[2][0] += a.z*b.x; acc[2][1] += a.z*b.y; acc[2][2] += a.z*b.z; acc[2][3] += a.z*b.w;
            acc[3][0] += a.w*b.x; acc[3][1] += a.w*b.y; acc[3][2] += a.w*b.z; acc[3][3] += a.w*b.w;
        }
        __syncthreads();
    }
    float* dst = part + (size_t)blockIdx.y * 64 * N;
#pragma unroll
    for (int i = 0; i < 4; i++) {
        float4 v = make_float4(acc[i][0], acc[i][1], acc[i][2], acc[i][3]);
        *(float4*)(dst + (size_t)(tm*4 + i) * N + nb + tn*4) = v;
    }
}

// =====================================================================
// Per-batch prep: combine up-proj x-partials, conv-state shift,
// causal conv + silu, block-diag q/k/v, gate dots, m_new/f_p/i_p.
// One block per batch, 256 threads.
// =====================================================================
__global__ void prep_kernel(const float* __restrict__ conv_state,
                            const float* __restrict__ conv_w,
                            const float* __restrict__ conv_b,
                            const float* __restrict__ Wq,
                            const float* __restrict__ Wk,
                            const float* __restrict__ Wv,
                            const float* __restrict__ Wi,
                            const float* __restrict__ bi,
                            const float* __restrict__ Wf,
                            const float* __restrict__ bf,
                            const float* __restrict__ m_in,
                            float* __restrict__ out_cs,
                            float* __restrict__ out_m)
{
    __shared__ float s_x[HIDD];
    __shared__ float s_conv[HIDD];
    __shared__ float s_qkv[3*HIDD];
    __shared__ float s_red[64];
    __shared__ float s_fin[8];

    int b = blockIdx.x;
    int tid = threadIdx.x;
    const float* cs  = conv_state + (size_t)b*KSS*HIDD;
    float*       ocs = out_cs     + (size_t)b*KSS*HIDD;
    const float* up  = g_up + (size_t)b*(2*HIDD);

    for (int j = tid; j < HIDD; j += 256) {
        float u0 = up[j], u1 = up[UPSZ + j], u2 = up[2*UPSZ + j], u3 = up[3*UPSZ + j];
        float c1 = cs[1*HIDD + j], c2 = cs[2*HIDD + j], c3 = cs[3*HIDD + j];
        float xj = u0 + u1 + u2 + u3;
        s_x[j] = xj;
        ocs[0*HIDD + j] = c1;
        ocs[1*HIDD + j] = c2;
        ocs[2*HIDD + j] = c3;
        ocs[3*HIDD + j] = xj;
        float conv = c1*conv_w[0*HIDD+j] + c2*conv_w[1*HIDD+j]
                   + c3*conv_w[2*HIDD+j] + xj*conv_w[3*HIDD+j] + conv_b[j];
        float act = conv / (1.f + expf(-conv));   // silu
        s_conv[j] = act;
        g_convact[b*HIDD + j] = act;
    }
    if (tid < NHH) g_den[b*NHH + tid] = 0.f;
    __syncthreads();

    // block-diagonal q/k/v (4x4 blocks)
    for (int j = tid; j < HIDD; j += 256) {
        int nb4 = j >> 2, e = j & 3;
        const float* wq = Wq + nb4*16 + e;
        const float* wk = Wk + nb4*16 + e;
        const float* wv = Wv + nb4*16 + e;
        float a0 = s_conv[nb4*4+0], a1 = s_conv[nb4*4+1], a2 = s_conv[nb4*4+2], a3 = s_conv[nb4*4+3];
        float x0 = s_x[nb4*4+0],    x1 = s_x[nb4*4+1],    x2 = s_x[nb4*4+2],    x3 = s_x[nb4*4+3];
        float q = a0*wq[0] + a1*wq[4] + a2*wq[8] + a3*wq[12];
        float k = a0*wk[0] + a1*wk[4] + a2*wk[8] + a3*wk[12];
        float v = x0*wv[0] + x1*wv[4] + x2*wv[8] + x3*wv[12];
        s_qkv[j]          = q;
        s_qkv[HIDD + j]   = k;
        s_qkv[2*HIDD + j] = v;
        g_q[b*HIDD + j] = q;
        g_k[b*HIDD + j] = k;
        g_v[b*HIDD + j] = v;
    }
    __syncthreads();

    // gates
    float pi[NHH] = {0,0,0,0};
    float pf[NHH] = {0,0,0,0};
    const float4* Wi4 = (const float4*)Wi;
    const float4* Wf4 = (const float4*)Wf;
    for (int j = tid; j < 3*HIDD; j += 256) {
        float val = s_qkv[j];
        float4 wi = Wi4[j];
        float4 wf = Wf4[j];
        pi[0] += val*wi.x; pi[1] += val*wi.y; pi[2] += val*wi.z; pi[3] += val*wi.w;
        pf[0] += val*wf.x; pf[1] += val*wf.y; pf[2] += val*wf.z; pf[3] += val*wf.w;
    }
#pragma unroll
    for (int off = 16; off; off >>= 1) {
#pragma unroll
        for (int h = 0; h < NHH; h++) {
            pi[h] += __shfl_down_sync(0xffffffffu, pi[h], off);
            pf[h] += __shfl_down_sync(0xffffffffu, pf[h], off);
        }
    }
    int lane = tid & 31, warp = tid >> 5;
    if (lane == 0) {
#pragma unroll
        for (int h = 0; h < NHH; h++) {
            s_red[warp*8 + h]     = pi[h];
            s_red[warp*8 + 4 + h] = pf[h];
        }
    }
    __syncthreads();
    if (tid < 8) {
        float s = 0.f;
#pragma unroll
        for (int w = 0; w < 8; w++) s += s_red[w*8 + tid];
        s_fin[tid] = s;
    }
    __syncthreads();
    if (tid < NHH) {
        int h = tid;
        float it = s_fin[h]     + bi[h];
        float ft = s_fin[4 + h] + bf[h];
        float logf = (ft > 0.f) ? -log1pf(expf(-ft)) : (ft - log1pf(expf(ft)));
        float mo = m_in[b*NHH + h];
        float mn = fmaxf(logf + mo, it);
        out_m[b*NHH + h] = mn;
        g_ip[b*NHH + h]  = expf(it - mn);
        g_fp[b*NHH + h]  = expf(logf + mo - mn);
        g_emn[b*NHH + h] = expf(-mn);
    }
}

// =====================================================================
// Fused C-state stream (the 537 MB). 64-row chunks: grid (8, B*NH)
// = 2048 blocks x 256 threads (R5-proven config).
// nom partials go to private per-chunk slices (plain STG — NO atomics).
// =====================================================================
__global__ void c_update_kernel(const float* __restrict__ C,
                                const float* __restrict__ n_in,
                                float* __restrict__ outC,
                                float* __restrict__ outN)
{
    int bh = blockIdx.y;
    int d0 = blockIdx.x * 64;
    int tid = threadIdx.x;  // 256

    __shared__ float s_kh[64];
    __shared__ float s_q[64];
    __shared__ float4 s_acc[128];

    float fp = g_fp[bh];
    float ip = g_ip[bh];

    if (tid < 64) {
        int d = d0 + tid;
        s_kh[tid] = g_k[bh*HDD + d] * INV_SQRT_HD;
        s_q[tid]  = g_q[bh*HDD + d];
    }
    __syncthreads();

    int tx = tid & 127;   // column group (x4 -> 512 cols)
    int ty = tid >> 7;    // row interleave
    float4 v4 = *(const float4*)(g_v + bh*HDD + tx*4);

    const float4* Cb = (const float4*)(C    + (size_t)bh*HDD*HDD);
    float4*       Ob = (float4*)      (outC + (size_t)bh*HDD*HDD);

    float4 acc = make_float4(0.f, 0.f, 0.f, 0.f);
#pragma unroll 8
    for (int dd = ty; dd < 64; dd += 2) {
        int d = d0 + dd;
        size_t idx = (size_t)d * (HDD/4) + tx;
        float4 c = __ldcs(Cb + idx);
        float ipk = ip * s_kh[dd];
        float4 cn;
        cn.x = fp*c.x + ipk*v4.x;
        cn.y = fp*c.y + ipk*v4.y;
        cn.z = fp*c.z + ipk*v4.z;
        cn.w = fp*c.w + ipk*v4.w;
        __stcs(Ob + idx, cn);
        float qd = s_q[dd];
        acc.x += qd*cn.x;
        acc.y += qd*cn.y;
        acc.z += qd*cn.z;
        acc.w += qd*cn.w;
    }

    // combine the two ty-halves in smem, then ONE clean STG per column group
    if (ty == 1) s_acc[tx] = acc;
    __syncthreads();
    if (ty == 0) {
        float4 o = s_acc[tx];
        o.x += acc.x; o.y += acc.y; o.z += acc.z; o.w += acc.w;
        *(float4*)(g_nomp + ((size_t)blockIdx.x * (BB*NHH) + bh) * HDD + tx*4) = o;
    }

    // n_new for the 64 rows this block owns + den partial
    if (tid < 64) {
        int d = d0 + tid;
        float nn = fp * n_in[bh*HDD + d] + ip * s_kh[tid];
        outN[bh*HDD + d] = nn;
        float p = s_q[tid] * nn;
#pragma unroll
        for (int off = 16; off; off >>= 1) p += __shfl_down_sync(0xffffffffu, p, off);
        if ((tid & 31) == 0) atomicAdd(&g_den[bh], p);
    }
}

// =====================================================================
// Finalize per (b,h): sum nom partials (8 chunks), h_tilde = nom/den,
// layernorm over HD, + skip*conv_act, * silu(z) -> g_h.
// grid = B*NH, 128 threads.
// =====================================================================
__global__ void finalize_kernel(const float* __restrict__ norm_scale,
                                const float* __restrict__ skip)
{
    int bh = blockIdx.x;
    int b = bh >> 2, h = bh & 3;
    int tid = threadIdx.x;  // 128

    __shared__ float ss[4], ss2[4];
    __shared__ float s_mean, s_rstd;

    // ---- issue independent loads up front ----
    float denp = g_den[bh];
    float emn  = g_emn[bh];
    // sum nom partials over 8 chunks (independent LDGs, MLP=8)
    float4 nom = make_float4(0.f, 0.f, 0.f, 0.f);
#pragma unroll
    for (int ch = 0; ch < NCHUNK; ch++) {
        float4 p = *(const float4*)(g_nomp + ((size_t)ch * (BB*NHH) + bh) * HDD + tid*4);
        nom.x += p.x; nom.y += p.y; nom.z += p.z; nom.w += p.w;
    }
    const float* zb = g_up + (size_t)b*(2*HIDD) + HIDD + h*HDD + tid*4;
    float4 za = *(const float4*)(zb + 0*UPSZ);
    float4 zc = *(const float4*)(zb + 1*UPSZ);
    float4 zd = *(const float4*)(zb + 2*UPSZ);
    float4 ze = *(const float4*)(zb + 3*UPSZ);
    float4 ca  = *(const float4*)(g_convact + b*HIDD + h*HDD + tid*4);
    float4 sk4 = *(const float4*)(skip + h*HDD + tid*4);
    float4 ns4 = *(const float4*)(norm_scale + h*HDD + tid*4);

    float den = fmaxf(fabsf(denp), emn) + EPSF;
    float inv = 1.f / den;

    float4 ht;
    ht.x = nom.x * inv; ht.y = nom.y * inv; ht.z = nom.z * inv; ht.w = nom.w * inv;

    float s  = ht.x + ht.y + ht.z + ht.w;
    float s2 = ht.x*ht.x + ht.y*ht.y + ht.z*ht.z + ht.w*ht.w;
#pragma unroll
    for (int off = 16; off; off >>= 1) {
        s  += __shfl_down_sync(0xffffffffu, s,  off);
        s2 += __shfl_down_sync(0xffffffffu, s2, off);
    }
    int lane = tid & 31, warp = tid >> 5;
    if (lane == 0) { ss[warp] = s; ss2[warp] = s2; }
    __syncthreads();
    if (tid == 0) {
        float S  = ss[0] + ss[1] + ss[2] + ss[3];
        float S2 = ss2[0] + ss2[1] + ss2[2] + ss2[3];
        float mean = S / (float)HDD;
        float var  = S2 / (float)HDD - mean*mean;
        s_mean = mean;
        s_rstd = rsqrtf(var + EPSF);
    }
    __syncthreads();
    float mean = s_mean, rstd = s_rstd;

    float zv[4];
    zv[0] = za.x + zc.x + zd.x + ze.x;
    zv[1] = za.y + zc.y + zd.y + ze.y;
    zv[2] = za.z + zc.z + zd.z + ze.z;
    zv[3] = za.w + zc.w + zd.w + ze.w;
    float cv[4] = {ca.x, ca.y, ca.z, ca.w};
    float sv[4] = {sk4.x, sk4.y, sk4.z, sk4.w};
    float nv[4] = {ns4.x, ns4.y, ns4.z, ns4.w};
    float hv[4] = {ht.x, ht.y, ht.z, ht.w};

    float4 outv;
    float* po = (float*)&outv;
#pragma unroll
    for (int i = 0; i < 4; i++) {
        float hn = (hv[i] - mean) * rstd * nv[i];
        float hh = hn + sv[i] * cv[i];
        float z = zv[i];
        hh *= z / (1.f + expf(-z));
        po[i] = hh;
    }
    *(float4*)(g_h + b*HIDD + h*HDD + tid*4) = outv;
}

// =====================================================================
// y = sum of down-proj split-K partials. 16384 float4s.
// =====================================================================
__global__ void combine_y_kernel(float* __restrict__ out_y)
{
    int i = blockIdx.x * 256 + threadIdx.x;   // over 16384 float4
    const float4* d = (const float4*)g_down;
    float4 s = make_float4(0.f, 0.f, 0.f, 0.f);
#pragma unroll
    for (int k = 0; k < DOWN_SPLITK; k++) {
        float4 v = d[(size_t)k * (DNSZ/4) + i];
        s.x += v.x; s.y += v.y; s.z += v.z; s.w += v.w;
    }
    ((float4*)out_y)[i] = s;
}

// =====================================================================
extern "C" void kernel_launch(void* const* d_in, const int* in_sizes, int n_in,
                              void* d_out, int out_size)
{
    const float* inputs     = (const float*)d_in[0];
    const float* C          = (const float*)d_in[1];
    const float* n_state    = (const float*)d_in[2];
    const float* m_state    = (const float*)d_in[3];
    const float* conv_state = (const float*)d_in[4];
    const float* W_up       = (const float*)d_in[5];
    const float* conv_w     = (const float*)d_in[6];
    const float* conv_b     = (const float*)d_in[7];
    const float* Wq         = (const float*)d_in[8];
    const float* Wk         = (const float*)d_in[9];
    const float* Wv         = (const float*)d_in[10];
    const float* Wi         = (const float*)d_in[11];
    const float* bi         = (const float*)d_in[12];
    const float* Wf         = (const float*)d_in[13];
    const float* bf         = (const float*)d_in[14];
    const float* norm_scale = (const float*)d_in[15];
    const float* skip       = (const float*)d_in[16];
    const float* W_down     = (const float*)d_in[17];

    float* out = (float*)d_out;
    // Output layout: y | C_new | n_new | m_new | conv_state_new
    float* out_y  = out;
    float* out_C  = out_y + (size_t)BB*FF;
    float* out_n  = out_C + (size_t)BB*NHH*HDD*HDD;
    float* out_m  = out_n + (size_t)BB*NHH*HDD;
    float* out_cs = out_m + (size_t)BB*NHH;

    float *pup, *pdown, *ph;
    cudaGetSymbolAddress((void**)&pup, g_up);
    cudaGetSymbolAddress((void**)&pdown, g_down);
    cudaGetSymbolAddress((void**)&ph, g_h);

    // 1) up-projection: [64,1024] @ [1024,4096] -> partials (split-K=4)
    sgemm_m64_part<<<dim3((2*HIDD)/64, UP_SPLITK), 256>>>(inputs, W_up, FF, 2*HIDD,
                                                          FF/UP_SPLITK, pup);

    // 2) conv / qkv / gates (combines x-partials)
    prep_kernel<<<BB, 256>>>(conv_state, conv_w, conv_b, Wq, Wk, Wv,
                             Wi, bi, Wf, bf, m_state, out_cs, out_m);

    // 3) fused C-state stream (the 537 MB) — atomic-free nom partials
    c_update_kernel<<<dim3(NCHUNK, BB*NHH), 256>>>(C, n_state, out_C, out_n);

    // 4) h_tilde + layernorm + skip + z-gate (sums nom + z partials)
    finalize_kernel<<<BB*NHH, 128>>>(norm_scale, skip);

    // 5) down-projection: [64,2048] @ [2048,1024] -> partials (split-K=8)
    sgemm_m64_part<<<dim3(FF/64, DOWN_SPLITK), 256>>>(ph, W_down, HIDD, FF,
                                                      HIDD/DOWN_SPLITK, pdown);

    // 6) combine y partials
    combine_y_kernel<<<(BB*FF/4)/256, 256>>>(out_y);
}

// round 10
// speedup vs baseline: 1.3549x; 1.2169x over previous
#include <cuda_runtime.h>
#include <math.h>
#include <stdint.h>

// Problem constants
#define BB    64
#define FF    1024
#define HIDD  2048
#define NHH   4
#define HDD   512
#define KSS   4
#define EPSF  1e-6f
#define INV_SQRT_HD 0.04419417382415922f   // 1/sqrt(512)

#define UP_SPLITK   4
#define DOWN_SPLITK 16
#define UPSZ   (BB*2*HIDD)          // 64*4096 elements per up partial slice
#define DNSZ   (BB*FF)              // 64*1024 elements per down partial slice

// ---------------- scratch (__device__ globals: allocation-free) ----------------
__device__ float g_up[UP_SPLITK*UPSZ];     // up-proj split-K partials (x|z)
__device__ float g_down[DOWN_SPLITK*DNSZ]; // down-proj split-K partials
__device__ float g_convact[BB*HIDD];
__device__ float g_q[BB*HIDD];
__device__ float g_k[BB*HIDD];
__device__ float g_v[BB*HIDD];
__device__ float g_fp[BB*NHH];
__device__ float g_ip[BB*NHH];
__device__ float g_emn[BB*NHH];  // exp(-m_new)
__device__ float g_nom[BB*HIDD]; // q^T @ C_new
__device__ float g_den[BB*NHH];  // q^T @ n_new
__device__ float g_h[BB*HIDD];

// ---------------- TF32 mma helpers ----------------
__device__ __forceinline__ uint32_t f2tf32(float x) {
    uint32_t u;
    asm("cvt.rna.tf32.f32 %0, %1;" : "=r"(u) : "f"(x));
    return u;
}
// split fp32 into hi (tf32) + lo (tf32 of residual); hi+lo ~ fp32 accurate
__device__ __forceinline__ void tf32_split(float x, uint32_t& hi, uint32_t& lo) {
    hi = f2tf32(x);
    float r = x - __uint_as_float(hi);
    lo = f2tf32(r);
}
__device__ __forceinline__ void mma_tf32(float* c, const uint32_t* a, const uint32_t* b) {
    asm volatile(
        "mma.sync.aligned.m16n8k8.row.col.f32.tf32.tf32.f32 "
        "{%0,%1,%2,%3}, {%4,%5,%6,%7}, {%8,%9}, {%0,%1,%2,%3};"
        : "+f"(c[0]), "+f"(c[1]), "+f"(c[2]), "+f"(c[3])
        : "r"(a[0]), "r"(a[1]), "r"(a[2]), "r"(a[3]), "r"(b[0]), "r"(b[1]));
}

// =====================================================================
// TF32 tensor-core GEMM, split-K partials: part[slice][64 x N]
// out[64 x N] = A[64 x K] @ B[K x N], both row-major.
// Block tile 64 x 64 x 32; 8 warps, each warp computes 16x32
// (4 subtiles of m16n8 per k8 step).  Hi/lo TF32 split -> fp32 accuracy
// (D = Ah*Bh + Ah*Bl + Al*Bh; dropped Al*Bl term ~2^-22).
// Smem row stride 72 floats (72 mod 32 = 8) -> conflict-free frag reads.
// =====================================================================
__global__ void gemm_tf32_part(const float* __restrict__ A, const float* __restrict__ Bm,
                               int K, int N, int Kslice, float* __restrict__ part)
{
    __shared__ float As[32][72];   // [k][m]
    __shared__ float Bs[32][72];   // [k][n]

    int tid  = threadIdx.x;          // 256
    int w    = tid >> 5;
    int lane = tid & 31;
    int g    = lane >> 2;            // 0..7
    int tI   = lane & 3;             // 0..3
    int mb   = (w & 3) * 16;         // warp m-block
    int nbw  = (w >> 2) * 32;        // warp n-block (2 warp cols)
    int nb   = blockIdx.x * 64;
    int kbeg = blockIdx.y * Kslice;

    float c[4][4] = {};              // 4 n-subtiles x 4 accum regs

    // global load assignments
    int larow = tid >> 2;            // 0..63 (A row)
    int lak   = (tid & 3) * 8;       // k offset within 32-chunk (coalesced 128B)
    int lbk   = tid >> 3;            // 0..31 (B k-row)
    int lbn   = (tid & 7) * 4;       // n offset (two float4 per thread)

    for (int k0 = kbeg; k0 < kbeg + Kslice; k0 += 32) {
        // A 64x32 -> As[k][m] (transposed store)
        float4 a4a = *(const float4*)(A + (size_t)larow * K + k0 + lak);
        float4 a4b = *(const float4*)(A + (size_t)larow * K + k0 + lak + 4);
        As[lak+0][larow] = a4a.x; As[lak+1][larow] = a4a.y;
        As[lak+2][larow] = a4a.z; As[lak+3][larow] = a4a.w;
        As[lak+4][larow] = a4b.x; As[lak+5][larow] = a4b.y;
        As[lak+6][larow] = a4b.z; As[lak+7][larow] = a4b.w;
        // B 32x64 -> Bs[k][n] (direct, coalesced)
        *(float4*)&Bs[lbk][lbn]
            = *(const float4*)(Bm + (size_t)(k0 + lbk) * N + nb + lbn);
        *(float4*)&Bs[lbk][lbn + 32]
            = *(const float4*)(Bm + (size_t)(k0 + lbk) * N + nb + lbn + 32);
        __syncthreads();

#pragma unroll
        for (int kk = 0; kk < 32; kk += 8) {
            // A fragment (fp32) -> hi/lo tf32
            float af0 = As[kk+tI  ][mb+g  ];
            float af1 = As[kk+tI  ][mb+g+8];
            float af2 = As[kk+tI+4][mb+g  ];
            float af3 = As[kk+tI+4][mb+g+8];
            uint32_t ah[4], al[4];
            tf32_split(af0, ah[0], al[0]);
            tf32_split(af1, ah[1], al[1]);
            tf32_split(af2, ah[2], al[2]);
            tf32_split(af3, ah[3], al[3]);
#pragma unroll
            for (int s = 0; s < 4; s++) {
                float bf0 = Bs[kk+tI  ][nbw + s*8 + g];
                float bf1 = Bs[kk+tI+4][nbw + s*8 + g];
                uint32_t bh[2], bl[2];
                tf32_split(bf0, bh[0], bl[0]);
                tf32_split(bf1, bh[1], bl[1]);
                mma_tf32(c[s], ah, bh);
                mma_tf32(c[s], ah, bl);
                mma_tf32(c[s], al, bh);
            }
        }
        __syncthreads();
    }

    // epilogue: write partial slice
    float* dst = part + (size_t)blockIdx.y * 64 * N;
#pragma unroll
    for (int s = 0; s < 4; s++) {
        int col = nb + nbw + s*8 + tI*2;
        *(float2*)(dst + (size_t)(mb + g    ) * N + col) = make_float2(c[s][0], c[s][1]);
        *(float2*)(dst + (size_t)(mb + g + 8) * N + col) = make_float2(c[s][2], c[s][3]);
    }
}

// =====================================================================
// Per-batch prep: combine up-proj x-partials, conv-state shift,
// causal conv + silu, block-diag q/k/v, gate dots, m_new/f_p/i_p.
// Zeroes g_nom / g_den. One block per batch, 256 threads.
// =====================================================================
__global__ void prep_kernel(const float* __restrict__ conv_state,
                            const float* __restrict__ conv_w,
                            const float* __restrict__ conv_b,
                            const float* __restrict__ Wq,
                            const float* __restrict__ Wk,
                            const float* __restrict__ Wv,
                            const float* __restrict__ Wi,
                            const float* __restrict__ bi,
                            const float* __restrict__ Wf,
                            const float* __restrict__ bf,
                            const float* __restrict__ m_in,
                            float* __restrict__ out_cs,
                            float* __restrict__ out_m)
{
    __shared__ float s_x[HIDD];
    __shared__ float s_conv[HIDD];
    __shared__ float s_qkv[3*HIDD];
    __shared__ float s_red[64];
    __shared__ float s_fin[8];

    int b = blockIdx.x;
    int tid = threadIdx.x;
    const float* cs  = conv_state + (size_t)b*KSS*HIDD;
    float*       ocs = out_cs     + (size_t)b*KSS*HIDD;
    const float* up  = g_up + (size_t)b*(2*HIDD);

    for (int j = tid; j < HIDD; j += 256) {
        float u0 = up[j], u1 = up[UPSZ + j], u2 = up[2*UPSZ + j], u3 = up[3*UPSZ + j];
        float c1 = cs[1*HIDD + j], c2 = cs[2*HIDD + j], c3 = cs[3*HIDD + j];
        float xj = u0 + u1 + u2 + u3;
        s_x[j] = xj;
        ocs[0*HIDD + j] = c1;
        ocs[1*HIDD + j] = c2;
        ocs[2*HIDD + j] = c3;
        ocs[3*HIDD + j] = xj;
        float conv = c1*conv_w[0*HIDD+j] + c2*conv_w[1*HIDD+j]
                   + c3*conv_w[2*HIDD+j] + xj*conv_w[3*HIDD+j] + conv_b[j];
        float act = conv / (1.f + expf(-conv));   // silu
        s_conv[j] = act;
        g_convact[b*HIDD + j] = act;
        g_nom[b*HIDD + j] = 0.f;
    }
    if (tid < NHH) g_den[b*NHH + tid] = 0.f;
    __syncthreads();

    // block-diagonal q/k/v (4x4 blocks)
    for (int j = tid; j < HIDD; j += 256) {
        int nb4 = j >> 2, e = j & 3;
        const float* wq = Wq + nb4*16 + e;
        const float* wk = Wk + nb4*16 + e;
        const float* wv = Wv + nb4*16 + e;
        float a0 = s_conv[nb4*4+0], a1 = s_conv[nb4*4+1], a2 = s_conv[nb4*4+2], a3 = s_conv[nb4*4+3];
        float x0 = s_x[nb4*4+0],    x1 = s_x[nb4*4+1],    x2 = s_x[nb4*4+2],    x3 = s_x[nb4*4+3];
        float q = a0*wq[0] + a1*wq[4] + a2*wq[8] + a3*wq[12];
        float k = a0*wk[0] + a1*wk[4] + a2*wk[8] + a3*wk[12];
        float v = x0*wv[0] + x1*wv[4] + x2*wv[8] + x3*wv[12];
        s_qkv[j]          = q;
        s_qkv[HIDD + j]   = k;
        s_qkv[2*HIDD + j] = v;
        g_q[b*HIDD + j] = q;
        g_k[b*HIDD + j] = k;
        g_v[b*HIDD + j] = v;
    }
    __syncthreads();

    // gates
    float pi[NHH] = {0,0,0,0};
    float pf[NHH] = {0,0,0,0};
    const float4* Wi4 = (const float4*)Wi;
    const float4* Wf4 = (const float4*)Wf;
    for (int j = tid; j < 3*HIDD; j += 256) {
        float val = s_qkv[j];
        float4 wi = Wi4[j];
        float4 wf = Wf4[j];
        pi[0] += val*wi.x; pi[1] += val*wi.y; pi[2] += val*wi.z; pi[3] += val*wi.w;
        pf[0] += val*wf.x; pf[1] += val*wf.y; pf[2] += val*wf.z; pf[3] += val*wf.w;
    }
#pragma unroll
    for (int off = 16; off; off >>= 1) {
#pragma unroll
        for (int h = 0; h < NHH; h++) {
            pi[h] += __shfl_down_sync(0xffffffffu, pi[h], off);
            pf[h] += __shfl_down_sync(0xffffffffu, pf[h], off);
        }
    }
    int lane = tid & 31, warp = tid >> 5;
    if (lane == 0) {
#pragma unroll
        for (int h = 0; h < NHH; h++) {
            s_red[warp*8 + h]     = pi[h];
            s_red[warp*8 + 4 + h] = pf[h];
        }
    }
    __syncthreads();
    if (tid < 8) {
        float s = 0.f;
#pragma unroll
        for (int w = 0; w < 8; w++) s += s_red[w*8 + tid];
        s_fin[tid] = s;
    }
    __syncthreads();
    if (tid < NHH) {
        int h = tid;
        float it = s_fin[h]     + bi[h];
        float ft = s_fin[4 + h] + bf[h];
        float logf = (ft > 0.f) ? -log1pf(expf(-ft)) : (ft - log1pf(expf(ft)));
        float mo = m_in[b*NHH + h];
        float mn = fmaxf(logf + mo, it);
        out_m[b*NHH + h] = mn;
        g_ip[b*NHH + h]  = expf(it - mn);
        g_fp[b*NHH + h]  = expf(logf + mo - mn);
        g_emn[b*NHH + h] = expf(-mn);
    }
}

// =====================================================================
// Fused C-state stream (the 537 MB). 64-row chunks: grid (8, B*NH)
// = 2048 blocks x 256 threads (R5-proven config, verbatim).
// =====================================================================
__global__ void c_update_kernel(const float* __restrict__ C,
                                const float* __restrict__ n_in,
                                float* __restrict__ outC,
                                float* __restrict__ outN)
{
    int bh = blockIdx.y;
    int d0 = blockIdx.x * 64;
    int tid = threadIdx.x;  // 256

    __shared__ float s_kh[64];
    __shared__ float s_q[64];

    float fp = g_fp[bh];
    float ip = g_ip[bh];

    if (tid < 64) {
        int d = d0 + tid;
        s_kh[tid] = g_k[bh*HDD + d] * INV_SQRT_HD;
        s_q[tid]  = g_q[bh*HDD + d];
    }
    __syncthreads();

    int tx = tid & 127;   // column group (x4 -> 512 cols)
    int ty = tid >> 7;    // row interleave
    float4 v4 = *(const float4*)(g_v + bh*HDD + tx*4);

    const float4* Cb = (const float4*)(C    + (size_t)bh*HDD*HDD);
    float4*       Ob = (float4*)      (outC + (size_t)bh*HDD*HDD);

    float4 acc = make_float4(0.f, 0.f, 0.f, 0.f);
#pragma unroll 8
    for (int dd = ty; dd < 64; dd += 2) {
        int d = d0 + dd;
        size_t idx = (size_t)d * (HDD/4) + tx;
        float4 c = __ldcs(Cb + idx);
        float ipk = ip * s_kh[dd];
        float4 cn;
        cn.x = fp*c.x + ipk*v4.x;
        cn.y = fp*c.y + ipk*v4.y;
        cn.z = fp*c.z + ipk*v4.z;
        cn.w = fp*c.w + ipk*v4.w;
        __stcs(Ob + idx, cn);
        float qd = s_q[dd];
        acc.x += qd*cn.x;
        acc.y += qd*cn.y;
        acc.z += qd*cn.z;
        acc.w += qd*cn.w;
    }
    float* nomp = g_nom + bh*HDD + tx*4;
    atomicAdd(nomp+0, acc.x);
    atomicAdd(nomp+1, acc.y);
    atomicAdd(nomp+2, acc.z);
    atomicAdd(nomp+3, acc.w);

    // n_new for the 64 rows this block owns + den partial
    if (tid < 64) {
        int d = d0 + tid;
        float nn = fp * n_in[bh*HDD + d] + ip * s_kh[tid];
        outN[bh*HDD + d] = nn;
        float p = s_q[tid] * nn;
#pragma unroll
        for (int off = 16; off; off >>= 1) p += __shfl_down_sync(0xffffffffu, p, off);
        if ((tid & 31) == 0) atomicAdd(&g_den[bh], p);
    }
}

// =====================================================================
// Finalize per (b,h): h_tilde = nom/(den+eps), layernorm over HD,
// + skip*conv_act, * silu(z) -> g_h.  grid = B*NH, 128 threads.
// =====================================================================
__global__ void finalize_kernel(const float* __restrict__ norm_scale,
                                const float* __restrict__ skip)
{
    int bh = blockIdx.x;
    int b = bh >> 2, h = bh & 3;
    int tid = threadIdx.x;  // 128

    __shared__ float ss[4], ss2[4];
    __shared__ float s_mean, s_rstd;

    // ---- issue ALL independent loads first ----
    float  denp = g_den[bh];
    float  emn  = g_emn[bh];
    float4 nom4 = *(const float4*)(g_nom + bh*HDD + tid*4);
    const float* zb = g_up + (size_t)b*(2*HIDD) + HIDD + h*HDD + tid*4;
    float4 za = *(const float4*)(zb + 0*UPSZ);
    float4 zc = *(const float4*)(zb + 1*UPSZ);
    float4 zd = *(const float4*)(zb + 2*UPSZ);
    float4 ze = *(const float4*)(zb + 3*UPSZ);
    float4 ca  = *(const float4*)(g_convact + b*HIDD + h*HDD + tid*4);
    float4 sk4 = *(const float4*)(skip + h*HDD + tid*4);
    float4 ns4 = *(const float4*)(norm_scale + h*HDD + tid*4);

    float den = fmaxf(fabsf(denp), emn) + EPSF;
    float inv = 1.f / den;

    float4 ht;
    ht.x = nom4.x * inv; ht.y = nom4.y * inv; ht.z = nom4.z * inv; ht.w = nom4.w * inv;

    float s  = ht.x + ht.y + ht.z + ht.w;
    float s2 = ht.x*ht.x + ht.y*ht.y + ht.z*ht.z + ht.w*ht.w;
#pragma unroll
    for (int off = 16; off; off >>= 1) {
        s  += __shfl_down_sync(0xffffffffu, s,  off);
        s2 += __shfl_down_sync(0xffffffffu, s2, off);
    }
    int lane = tid & 31, warp = tid >> 5;
    if (lane == 0) { ss[warp] = s; ss2[warp] = s2; }
    __syncthreads();
    if (tid == 0) {
        float S  = ss[0] + ss[1] + ss[2] + ss[3];
        float S2 = ss2[0] + ss2[1] + ss2[2] + ss2[3];
        float mean = S / (float)HDD;
        float var  = S2 / (float)HDD - mean*mean;
        s_mean = mean;
        s_rstd = rsqrtf(var + EPSF);
    }
    __syncthreads();
    float mean = s_mean, rstd = s_rstd;

    float zv[4];
    zv[0] = za.x + zc.x + zd.x + ze.x;
    zv[1] = za.y + zc.y + zd.y + ze.y;
    zv[2] = za.z + zc.z + zd.z + ze.z;
    zv[3] = za.w + zc.w + zd.w + ze.w;
    float cv[4] = {ca.x, ca.y, ca.z, ca.w};
    float sv[4] = {sk4.x, sk4.y, sk4.z, sk4.w};
    float nv[4] = {ns4.x, ns4.y, ns4.z, ns4.w};
    float hv[4] = {ht.x, ht.y, ht.z, ht.w};

    float4 outv;
    float* po = (float*)&outv;
#pragma unroll
    for (int i = 0; i < 4; i++) {
        float hn = (hv[i] - mean) * rstd * nv[i];
        float hh = hn + sv[i] * cv[i];
        float z = zv[i];
        hh *= z / (1.f + expf(-z));
        po[i] = hh;
    }
    *(float4*)(g_h + b*HIDD + h*HDD + tid*4) = outv;
}

// =====================================================================
// y = sum of down-proj split-K partials. 16384 float4s.
// =====================================================================
__global__ void combine_y_kernel(float* __restrict__ out_y)
{
    int i = blockIdx.x * 256 + threadIdx.x;   // over 16384 float4
    const float4* d = (const float4*)g_down;
    float4 s = make_float4(0.f, 0.f, 0.f, 0.f);
#pragma unroll
    for (int k = 0; k < DOWN_SPLITK; k++) {
        float4 v = d[(size_t)k * (DNSZ/4) + i];
        s.x += v.x; s.y += v.y; s.z += v.z; s.w += v.w;
    }
    ((float4*)out_y)[i] = s;
}

// =====================================================================
extern "C" void kernel_launch(void* const* d_in, const int* in_sizes, int n_in,
                              void* d_out, int out_size)
{
    const float* inputs     = (const float*)d_in[0];
    const float* C          = (const float*)d_in[1];
    const float* n_state    = (const float*)d_in[2];
    const float* m_state    = (const float*)d_in[3];
    const float* conv_state = (const float*)d_in[4];
    const float* W_up       = (const float*)d_in[5];
    const float* conv_w     = (const float*)d_in[6];
    const float* conv_b     = (const float*)d_in[7];
    const float* Wq         = (const float*)d_in[8];
    const float* Wk         = (const float*)d_in[9];
    const float* Wv         = (const float*)d_in[10];
    const float* Wi         = (const float*)d_in[11];
    const float* bi         = (const float*)d_in[12];
    const float* Wf         = (const float*)d_in[13];
    const float* bf         = (const float*)d_in[14];
    const float* norm_scale = (const float*)d_in[15];
    const float* skip       = (const float*)d_in[16];
    const float* W_down     = (const float*)d_in[17];

    float* out = (float*)d_out;
    // Output layout: y | C_new | n_new | m_new | conv_state_new
    float* out_y  = out;
    float* out_C  = out_y + (size_t)BB*FF;
    float* out_n  = out_C + (size_t)BB*NHH*HDD*HDD;
    float* out_m  = out_n + (size_t)BB*NHH*HDD;
    float* out_cs = out_m + (size_t)BB*NHH;

    float *pup, *pdown, *ph;
    cudaGetSymbolAddress((void**)&pup, g_up);
    cudaGetSymbolAddress((void**)&pdown, g_down);
    cudaGetSymbolAddress((void**)&ph, g_h);

    // 1) up-projection: [64,1024] @ [1024,4096] -> partials (split-K=4, TF32 hi/lo)
    gemm_tf32_part<<<dim3((2*HIDD)/64, UP_SPLITK), 256>>>(inputs, W_up, FF, 2*HIDD,
                                                          FF/UP_SPLITK, pup);

    // 2) conv / qkv / gates (combines x-partials)
    prep_kernel<<<BB, 256>>>(conv_state, conv_w, conv_b, Wq, Wk, Wv,
                             Wi, bi, Wf, bf, m_state, out_cs, out_m);

    // 3) fused C-state stream (the 537 MB)
    c_update_kernel<<<dim3(8, BB*NHH), 256>>>(C, n_state, out_C, out_n);

    // 4) h_tilde + layernorm + skip + z-gate
    finalize_kernel<<<BB*NHH, 128>>>(norm_scale, skip);

    // 5) down-projection: [64,2048] @ [2048,1024] -> partials (split-K=16, TF32 hi/lo)
    gemm_tf32_part<<<dim3(FF/64, DOWN_SPLITK), 256>>>(ph, W_down, HIDD, FF,
                                                      HIDD/DOWN_SPLITK, pdown);

    // 6) combine y partials
    combine_y_kernel<<<(BB*FF/4)/256, 256>>>(out_y);
}

// round 11
// speedup vs baseline: 1.4549x; 1.0738x over previous
#include <cuda_runtime.h>
#include <math.h>
#include <stdint.h>

// Problem constants
#define BB    64
#define FF    1024
#define HIDD  2048
#define NHH   4
#define HDD   512
#define KSS   4
#define EPSF  1e-6f
#define INV_SQRT_HD 0.04419417382415922f   // 1/sqrt(512)

#define UP_SPLITK   4
#define DOWN_SPLITK 16
#define UPSZ   (BB*2*HIDD)          // 64*4096 elements per up partial slice
#define DNSZ   (BB*FF)              // 64*1024 elements per down partial slice

// ---------------- scratch (__device__ globals: allocation-free) ----------------
__device__ float g_up[UP_SPLITK*UPSZ];     // up-proj split-K partials (x|z)
__device__ float g_down[DOWN_SPLITK*DNSZ]; // down-proj split-K partials
__device__ float g_convact[BB*HIDD];
__device__ float g_q[BB*HIDD];
__device__ float g_k[BB*HIDD];
__device__ float g_v[BB*HIDD];
__device__ float g_fp[BB*NHH];
__device__ float g_ip[BB*NHH];
__device__ float g_emn[BB*NHH];  // exp(-m_new)
__device__ float g_nom[BB*HIDD]; // q^T @ C_new
__device__ float g_den[BB*NHH];  // q^T @ n_new
__device__ float g_h[BB*HIDD];

// ---------------- TF32 mma helpers ----------------
__device__ __forceinline__ uint32_t f2tf32(float x) {
    uint32_t u;
    asm("cvt.rna.tf32.f32 %0, %1;" : "=r"(u) : "f"(x));
    return u;
}
// split fp32 into hi (tf32) + lo (tf32 of residual); hi+lo ~ fp32 accurate
__device__ __forceinline__ void tf32_split(float x, uint32_t& hi, uint32_t& lo) {
    hi = f2tf32(x);
    float r = x - __uint_as_float(hi);
    lo = f2tf32(r);
}
__device__ __forceinline__ void mma_tf32(float* c, const uint32_t* a, const uint32_t* b) {
    asm volatile(
        "mma.sync.aligned.m16n8k8.row.col.f32.tf32.tf32.f32 "
        "{%0,%1,%2,%3}, {%4,%5,%6,%7}, {%8,%9}, {%0,%1,%2,%3};"
        : "+f"(c[0]), "+f"(c[1]), "+f"(c[2]), "+f"(c[3])
        : "r"(a[0]), "r"(a[1]), "r"(a[2]), "r"(a[3]), "r"(b[0]), "r"(b[1]));
}

// =====================================================================
// TF32 tensor-core GEMM, split-K partials: part[slice][64 x N]
// (unchanged from R10 — proven)
// =====================================================================
__global__ void gemm_tf32_part(const float* __restrict__ A, const float* __restrict__ Bm,
                               int K, int N, int Kslice, float* __restrict__ part)
{
    __shared__ float As[32][72];   // [k][m]
    __shared__ float Bs[32][72];   // [k][n]

    int tid  = threadIdx.x;          // 256
    int w    = tid >> 5;
    int lane = tid & 31;
    int g    = lane >> 2;            // 0..7
    int tI   = lane & 3;             // 0..3
    int mb   = (w & 3) * 16;         // warp m-block
    int nbw  = (w >> 2) * 32;        // warp n-block
    int nb   = blockIdx.x * 64;
    int kbeg = blockIdx.y * Kslice;

    float c[4][4] = {};

    int larow = tid >> 2;
    int lak   = (tid & 3) * 8;
    int lbk   = tid >> 3;
    int lbn   = (tid & 7) * 4;

    for (int k0 = kbeg; k0 < kbeg + Kslice; k0 += 32) {
        float4 a4a = *(const float4*)(A + (size_t)larow * K + k0 + lak);
        float4 a4b = *(const float4*)(A + (size_t)larow * K + k0 + lak + 4);
        As[lak+0][larow] = a4a.x; As[lak+1][larow] = a4a.y;
        As[lak+2][larow] = a4a.z; As[lak+3][larow] = a4a.w;
        As[lak+4][larow] = a4b.x; As[lak+5][larow] = a4b.y;
        As[lak+6][larow] = a4b.z; As[lak+7][larow] = a4b.w;
        *(float4*)&Bs[lbk][lbn]
            = *(const float4*)(Bm + (size_t)(k0 + lbk) * N + nb + lbn);
        *(float4*)&Bs[lbk][lbn + 32]
            = *(const float4*)(Bm + (size_t)(k0 + lbk) * N + nb + lbn + 32);
        __syncthreads();

#pragma unroll
        for (int kk = 0; kk < 32; kk += 8) {
            float af0 = As[kk+tI  ][mb+g  ];
            float af1 = As[kk+tI  ][mb+g+8];
            float af2 = As[kk+tI+4][mb+g  ];
            float af3 = As[kk+tI+4][mb+g+8];
            uint32_t ah[4], al[4];
            tf32_split(af0, ah[0], al[0]);
            tf32_split(af1, ah[1], al[1]);
            tf32_split(af2, ah[2], al[2]);
            tf32_split(af3, ah[3], al[3]);
#pragma unroll
            for (int s = 0; s < 4; s++) {
                float bf0 = Bs[kk+tI  ][nbw + s*8 + g];
                float bf1 = Bs[kk+tI+4][nbw + s*8 + g];
                uint32_t bh[2], bl[2];
                tf32_split(bf0, bh[0], bl[0]);
                tf32_split(bf1, bh[1], bl[1]);
                mma_tf32(c[s], ah, bh);
                mma_tf32(c[s], ah, bl);
                mma_tf32(c[s], al, bh);
            }
        }
        __syncthreads();
    }

    float* dst = part + (size_t)blockIdx.y * 64 * N;
#pragma unroll
    for (int s = 0; s < 4; s++) {
        int col = nb + nbw + s*8 + tI*2;
        *(float2*)(dst + (size_t)(mb + g    ) * N + col) = make_float2(c[s][0], c[s][1]);
        *(float2*)(dst + (size_t)(mb + g + 8) * N + col) = make_float2(c[s][2], c[s][3]);
    }
}

// =====================================================================
// Per-batch prep (unchanged from R10 — proven)
// =====================================================================
__global__ void prep_kernel(const float* __restrict__ conv_state,
                            const float* __restrict__ conv_w,
                            const float* __restrict__ conv_b,
                            const float* __restrict__ Wq,
                            const float* __restrict__ Wk,
                            const float* __restrict__ Wv,
                            const float* __restrict__ Wi,
                            const float* __restrict__ bi,
                            const float* __restrict__ Wf,
                            const float* __restrict__ bf,
                            const float* __restrict__ m_in,
                            float* __restrict__ out_cs,
                            float* __restrict__ out_m)
{
    __shared__ float s_x[HIDD];
    __shared__ float s_conv[HIDD];
    __shared__ float s_qkv[3*HIDD];
    __shared__ float s_red[64];
    __shared__ float s_fin[8];

    int b = blockIdx.x;
    int tid = threadIdx.x;
    const float* cs  = conv_state + (size_t)b*KSS*HIDD;
    float*       ocs = out_cs     + (size_t)b*KSS*HIDD;
    const float* up  = g_up + (size_t)b*(2*HIDD);

    for (int j = tid; j < HIDD; j += 256) {
        float u0 = up[j], u1 = up[UPSZ + j], u2 = up[2*UPSZ + j], u3 = up[3*UPSZ + j];
        float c1 = cs[1*HIDD + j], c2 = cs[2*HIDD + j], c3 = cs[3*HIDD + j];
        float xj = u0 + u1 + u2 + u3;
        s_x[j] = xj;
        ocs[0*HIDD + j] = c1;
        ocs[1*HIDD + j] = c2;
        ocs[2*HIDD + j] = c3;
        ocs[3*HIDD + j] = xj;
        float conv = c1*conv_w[0*HIDD+j] + c2*conv_w[1*HIDD+j]
                   + c3*conv_w[2*HIDD+j] + xj*conv_w[3*HIDD+j] + conv_b[j];
        float act = conv / (1.f + expf(-conv));   // silu
        s_conv[j] = act;
        g_convact[b*HIDD + j] = act;
        g_nom[b*HIDD + j] = 0.f;
    }
    if (tid < NHH) g_den[b*NHH + tid] = 0.f;
    __syncthreads();

    // block-diagonal q/k/v (4x4 blocks)
    for (int j = tid; j < HIDD; j += 256) {
        int nb4 = j >> 2, e = j & 3;
        const float* wq = Wq + nb4*16 + e;
        const float* wk = Wk + nb4*16 + e;
        const float* wv = Wv + nb4*16 + e;
        float a0 = s_conv[nb4*4+0], a1 = s_conv[nb4*4+1], a2 = s_conv[nb4*4+2], a3 = s_conv[nb4*4+3];
        float x0 = s_x[nb4*4+0],    x1 = s_x[nb4*4+1],    x2 = s_x[nb4*4+2],    x3 = s_x[nb4*4+3];
        float q = a0*wq[0] + a1*wq[4] + a2*wq[8] + a3*wq[12];
        float k = a0*wk[0] + a1*wk[4] + a2*wk[8] + a3*wk[12];
        float v = x0*wv[0] + x1*wv[4] + x2*wv[8] + x3*wv[12];
        s_qkv[j]          = q;
        s_qkv[HIDD + j]   = k;
        s_qkv[2*HIDD + j] = v;
        g_q[b*HIDD + j] = q;
        g_k[b*HIDD + j] = k;
        g_v[b*HIDD + j] = v;
    }
    __syncthreads();

    // gates
    float pi[NHH] = {0,0,0,0};
    float pf[NHH] = {0,0,0,0};
    const float4* Wi4 = (const float4*)Wi;
    const float4* Wf4 = (const float4*)Wf;
    for (int j = tid; j < 3*HIDD; j += 256) {
        float val = s_qkv[j];
        float4 wi = Wi4[j];
        float4 wf = Wf4[j];
        pi[0] += val*wi.x; pi[1] += val*wi.y; pi[2] += val*wi.z; pi[3] += val*wi.w;
        pf[0] += val*wf.x; pf[1] += val*wf.y; pf[2] += val*wf.z; pf[3] += val*wf.w;
    }
#pragma unroll
    for (int off = 16; off; off >>= 1) {
#pragma unroll
        for (int h = 0; h < NHH; h++) {
            pi[h] += __shfl_down_sync(0xffffffffu, pi[h], off);
            pf[h] += __shfl_down_sync(0xffffffffu, pf[h], off);
        }
    }
    int lane = tid & 31, warp = tid >> 5;
    if (lane == 0) {
#pragma unroll
        for (int h = 0; h < NHH; h++) {
            s_red[warp*8 + h]     = pi[h];
            s_red[warp*8 + 4 + h] = pf[h];
        }
    }
    __syncthreads();
    if (tid < 8) {
        float s = 0.f;
#pragma unroll
        for (int w = 0; w < 8; w++) s += s_red[w*8 + tid];
        s_fin[tid] = s;
    }
    __syncthreads();
    if (tid < NHH) {
        int h = tid;
        float it = s_fin[h]     + bi[h];
        float ft = s_fin[4 + h] + bf[h];
        float logf = (ft > 0.f) ? -log1pf(expf(-ft)) : (ft - log1pf(expf(ft)));
        float mo = m_in[b*NHH + h];
        float mn = fmaxf(logf + mo, it);
        out_m[b*NHH + h] = mn;
        g_ip[b*NHH + h]  = expf(it - mn);
        g_fp[b*NHH + h]  = expf(logf + mo - mn);
        g_emn[b*NHH + h] = expf(-mn);
    }
}

// =====================================================================
// Fused C-state stream (the 537 MB).  grid (8, B*NH) x 256 threads.
// NEW: 32B per thread per row (2x LDG.128 / 2x STG.128), fully unrolled
// 16-row loop with explicit next-row preload (deep MLP), smem tree
// reduction of nom partials (atomic count halved vs R5).
// =====================================================================
__global__ void c_update_kernel(const float* __restrict__ C,
                                const float* __restrict__ n_in,
                                float* __restrict__ outC,
                                float* __restrict__ outN)
{
    int bh = blockIdx.y;
    int d0 = blockIdx.x * 64;
    int tid = threadIdx.x;  // 256

    __shared__ float s_kh[64];
    __shared__ float s_q[64];
    __shared__ float4 s_part[256];   // 2 x (64 tx * 2 float4) reduction buffer

    float fp = g_fp[bh];
    float ip = g_ip[bh];

    if (tid < 64) {
        int d = d0 + tid;
        s_kh[tid] = g_k[bh*HDD + d] * INV_SQRT_HD;
        s_q[tid]  = g_q[bh*HDD + d];
    }
    __syncthreads();

    int tx = tid & 63;    // column segment: 8 floats (32B) each -> 512 cols
    int ty = tid >> 6;    // 0..3 row interleave

    float4 va = *(const float4*)(g_v + bh*HDD + tx*8);
    float4 vb = *(const float4*)(g_v + bh*HDD + tx*8 + 4);

    const float4* Cb = (const float4*)(C    + (size_t)bh*HDD*HDD) + tx*2;
    float4*       Ob = (float4*)      (outC + (size_t)bh*HDD*HDD) + tx*2;

    float4 accA = make_float4(0.f, 0.f, 0.f, 0.f);
    float4 accB = make_float4(0.f, 0.f, 0.f, 0.f);

    const size_t rs = (size_t)4 * (HDD/4);   // 4-row stride in float4 units
    int dd = ty;
    size_t idx = (size_t)(d0 + dd) * (HDD/4);
    float4 c0 = __ldcs(Cb + idx);
    float4 c1 = __ldcs(Cb + idx + 1);

#pragma unroll
    for (int it = 0; it < 16; it++) {
        size_t idxn = idx + rs;
        float4 n0, n1;
        if (it < 15) {                 // static under full unroll
            n0 = __ldcs(Cb + idxn);
            n1 = __ldcs(Cb + idxn + 1);
        }
        float ipk = ip * s_kh[dd];
        float qd  = s_q[dd];
        float4 cn0, cn1;
        cn0.x = fp*c0.x + ipk*va.x;  cn0.y = fp*c0.y + ipk*va.y;
        cn0.z = fp*c0.z + ipk*va.z;  cn0.w = fp*c0.w + ipk*va.w;
        cn1.x = fp*c1.x + ipk*vb.x;  cn1.y = fp*c1.y + ipk*vb.y;
        cn1.z = fp*c1.z + ipk*vb.z;  cn1.w = fp*c1.w + ipk*vb.w;
        __stcs(Ob + idx,     cn0);
        __stcs(Ob + idx + 1, cn1);
        accA.x += qd*cn0.x; accA.y += qd*cn0.y; accA.z += qd*cn0.z; accA.w += qd*cn0.w;
        accB.x += qd*cn1.x; accB.y += qd*cn1.y; accB.z += qd*cn1.z; accB.w += qd*cn1.w;
        c0 = n0; c1 = n1; idx = idxn; dd += 4;
    }

    // ---- reduce acc over ty (4 -> 1) via smem tree, then single STG-atomic set ----
    if (ty >= 2) {
        s_part[((ty-2)*64 + tx)*2    ] = accA;
        s_part[((ty-2)*64 + tx)*2 + 1] = accB;
    }
    __syncthreads();
    if (ty < 2) {
        float4 pA = s_part[(ty*64 + tx)*2];
        float4 pB = s_part[(ty*64 + tx)*2 + 1];
        accA.x += pA.x; accA.y += pA.y; accA.z += pA.z; accA.w += pA.w;
        accB.x += pB.x; accB.y += pB.y; accB.z += pB.z; accB.w += pB.w;
    }
    __syncthreads();
    if (ty == 1) {
        s_part[tx*2]     = accA;
        s_part[tx*2 + 1] = accB;
    }
    __syncthreads();
    if (ty == 0) {
        float4 pA = s_part[tx*2];
        float4 pB = s_part[tx*2 + 1];
        accA.x += pA.x; accA.y += pA.y; accA.z += pA.z; accA.w += pA.w;
        accB.x += pB.x; accB.y += pB.y; accB.z += pB.z; accB.w += pB.w;
        float* nomp = g_nom + bh*HDD + tx*8;
        atomicAdd(nomp+0, accA.x); atomicAdd(nomp+1, accA.y);
        atomicAdd(nomp+2, accA.z); atomicAdd(nomp+3, accA.w);
        atomicAdd(nomp+4, accB.x); atomicAdd(nomp+5, accB.y);
        atomicAdd(nomp+6, accB.z); atomicAdd(nomp+7, accB.w);
    }

    // n_new for the 64 rows this block owns + den partial
    if (tid < 64) {
        int d = d0 + tid;
        float nn = fp * n_in[bh*HDD + d] + ip * s_kh[tid];
        outN[bh*HDD + d] = nn;
        float p = s_q[tid] * nn;
#pragma unroll
        for (int off = 16; off; off >>= 1) p += __shfl_down_sync(0xffffffffu, p, off);
        if ((tid & 31) == 0) atomicAdd(&g_den[bh], p);
    }
}

// =====================================================================
// Finalize (unchanged from R10 — proven)
// =====================================================================
__global__ void finalize_kernel(const float* __restrict__ norm_scale,
                                const float* __restrict__ skip)
{
    int bh = blockIdx.x;
    int b = bh >> 2, h = bh & 3;
    int tid = threadIdx.x;  // 128

    __shared__ float ss[4], ss2[4];
    __shared__ float s_mean, s_rstd;

    float  denp = g_den[bh];
    float  emn  = g_emn[bh];
    float4 nom4 = *(const float4*)(g_nom + bh*HDD + tid*4);
    const float* zb = g_up + (size_t)b*(2*HIDD) + HIDD + h*HDD + tid*4;
    float4 za = *(const float4*)(zb + 0*UPSZ);
    float4 zc = *(const float4*)(zb + 1*UPSZ);
    float4 zd = *(const float4*)(zb + 2*UPSZ);
    float4 ze = *(const float4*)(zb + 3*UPSZ);
    float4 ca  = *(const float4*)(g_convact + b*HIDD + h*HDD + tid*4);
    float4 sk4 = *(const float4*)(skip + h*HDD + tid*4);
    float4 ns4 = *(const float4*)(norm_scale + h*HDD + tid*4);

    float den = fmaxf(fabsf(denp), emn) + EPSF;
    float inv = 1.f / den;

    float4 ht;
    ht.x = nom4.x * inv; ht.y = nom4.y * inv; ht.z = nom4.z * inv; ht.w = nom4.w * inv;

    float s  = ht.x + ht.y + ht.z + ht.w;
    float s2 = ht.x*ht.x + ht.y*ht.y + ht.z*ht.z + ht.w*ht.w;
#pragma unroll
    for (int off = 16; off; off >>= 1) {
        s  += __shfl_down_sync(0xffffffffu, s,  off);
        s2 += __shfl_down_sync(0xffffffffu, s2, off);
    }
    int lane = tid & 31, warp = tid >> 5;
    if (lane == 0) { ss[warp] = s; ss2[warp] = s2; }
    __syncthreads();
    if (tid == 0) {
        float S  = ss[0] + ss[1] + ss[2] + ss[3];
        float S2 = ss2[0] + ss2[1] + ss2[2] + ss2[3];
        float mean = S / (float)HDD;
        float var  = S2 / (float)HDD - mean*mean;
        s_mean = mean;
        s_rstd = rsqrtf(var + EPSF);
    }
    __syncthreads();
    float mean = s_mean, rstd = s_rstd;

    float zv[4];
    zv[0] = za.x + zc.x + zd.x + ze.x;
    zv[1] = za.y + zc.y + zd.y + ze.y;
    zv[2] = za.z + zc.z + zd.z + ze.z;
    zv[3] = za.w + zc.w + zd.w + ze.w;
    float cv[4] = {ca.x, ca.y, ca.z, ca.w};
    float sv[4] = {sk4.x, sk4.y, sk4.z, sk4.w};
    float nv[4] = {ns4.x, ns4.y, ns4.z, ns4.w};
    float hv[4] = {ht.x, ht.y, ht.z, ht.w};

    float4 outv;
    float* po = (float*)&outv;
#pragma unroll
    for (int i = 0; i < 4; i++) {
        float hn = (hv[i] - mean) * rstd * nv[i];
        float hh = hn + sv[i] * cv[i];
        float z = zv[i];
        hh *= z / (1.f + expf(-z));
        po[i] = hh;
    }
    *(float4*)(g_h + b*HIDD + h*HDD + tid*4) = outv;
}

// =====================================================================
// y = sum of down-proj split-K partials. 16384 float4s.
// =====================================================================
__global__ void combine_y_kernel(float* __restrict__ out_y)
{
    int i = blockIdx.x * 256 + threadIdx.x;   // over 16384 float4
    const float4* d = (const float4*)g_down;
    float4 s = make_float4(0.f, 0.f, 0.f, 0.f);
#pragma unroll
    for (int k = 0; k < DOWN_SPLITK; k++) {
        float4 v = d[(size_t)k * (DNSZ/4) + i];
        s.x += v.x; s.y += v.y; s.z += v.z; s.w += v.w;
    }
    ((float4*)out_y)[i] = s;
}

// =====================================================================
extern "C" void kernel_launch(void* const* d_in, const int* in_sizes, int n_in,
                              void* d_out, int out_size)
{
    const float* inputs     = (const float*)d_in[0];
    const float* C          = (const float*)d_in[1];
    const float* n_state    = (const float*)d_in[2];
    const float* m_state    = (const float*)d_in[3];
    const float* conv_state = (const float*)d_in[4];
    const float* W_up       = (const float*)d_in[5];
    const float* conv_w     = (const float*)d_in[6];
    const float* conv_b     = (const float*)d_in[7];
    const float* Wq         = (const float*)d_in[8];
    const float* Wk         = (const float*)d_in[9];
    const float* Wv         = (const float*)d_in[10];
    const float* Wi         = (const float*)d_in[11];
    const float* bi         = (const float*)d_in[12];
    const float* Wf         = (const float*)d_in[13];
    const float* bf         = (const float*)d_in[14];
    const float* norm_scale = (const float*)d_in[15];
    const float* skip       = (const float*)d_in[16];
    const float* W_down     = (const float*)d_in[17];

    float* out = (float*)d_out;
    // Output layout: y | C_new | n_new | m_new | conv_state_new
    float* out_y  = out;
    float* out_C  = out_y + (size_t)BB*FF;
    float* out_n  = out_C + (size_t)BB*NHH*HDD*HDD;
    float* out_m  = out_n + (size_t)BB*NHH*HDD;
    float* out_cs = out_m + (size_t)BB*NHH;

    float *pup, *pdown, *ph;
    cudaGetSymbolAddress((void**)&pup, g_up);
    cudaGetSymbolAddress((void**)&pdown, g_down);
    cudaGetSymbolAddress((void**)&ph, g_h);

    // 1) up-projection: [64,1024] @ [1024,4096] -> partials (split-K=4, TF32 hi/lo)
    gemm_tf32_part<<<dim3((2*HIDD)/64, UP_SPLITK), 256>>>(inputs, W_up, FF, 2*HIDD,
                                                          FF/UP_SPLITK, pup);

    // 2) conv / qkv / gates (combines x-partials)
    prep_kernel<<<BB, 256>>>(conv_state, conv_w, conv_b, Wq, Wk, Wv,
                             Wi, bi, Wf, bf, m_state, out_cs, out_m);

    // 3) fused C-state stream (the 537 MB), wide accesses + deep MLP
    c_update_kernel<<<dim3(8, BB*NHH), 256>>>(C, n_state, out_C, out_n);

    // 4) h_tilde + layernorm + skip + z-gate
    finalize_kernel<<<BB*NHH, 128>>>(norm_scale, skip);

    // 5) down-projection: [64,2048] @ [2048,1024] -> partials (split-K=16, TF32 hi/lo)
    gemm_tf32_part<<<dim3(FF/64, DOWN_SPLITK), 256>>>(ph, W_down, HIDD, FF,
                                                      HIDD/DOWN_SPLITK, pdown);

    // 6) combine y partials
    combine_y_kernel<<<(BB*FF/4)/256, 256>>>(out_y);
}